// round 9
// baseline (speedup 1.0000x reference)
#include <cuda_runtime.h>

#define NN 50000
#define NE 800000
#define F0 100
#define F1 256
#define F2 128

#define SCAN_T 1024
#define PER ((NN + SCAN_T - 1) / SCAN_T)   // 49 nodes per scan thread

// ---------------- scratch (static device globals; no allocations) ----------
__device__ __align__(16) float d_dinv[NN];                 // rsqrt(deg)
__device__ int   d_deg[NN];                                // int degree (no self-loop)
__device__ int   d_rowptr[NN + 1];                         // CSR row pointers (by dst)
__device__ int   d_cursor[NN];                             // bump allocator
__device__ int   d_csr[NE];                                // src ids grouped by dst
__device__ __align__(16) float d_g0[(size_t)NN * F0];      // dinv-scaled x
__device__ __align__(16) float d_agg0[(size_t)NN * F0];    // layer-1 aggregation
__device__ __align__(16) float d_relu1[(size_t)NN * F1];   // layer-1 activation
__device__ __align__(16) float d_g2[(size_t)NN * F2];      // dinv-scaled h2

// ---------------- CSR build -------------------------------------------------
__global__ void k_zero_deg() {
    int i = blockIdx.x * blockDim.x + threadIdx.x;
    if (i < NN) d_deg[i] = 0;
}

__global__ void k_count(const int* __restrict__ dst) {
    int e = blockIdx.x * blockDim.x + threadIdx.x;
    if (e < NE) {
        int d = dst[e];
        if ((unsigned)d < NN) atomicAdd(&d_deg[d], 1);
    }
}

// single-block exclusive scan over d_deg -> d_rowptr / d_cursor; also dinv.
__global__ void k_scan() {
    __shared__ int sums[SCAN_T];
    int t = threadIdx.x;
    int base = t * PER;
    int local[PER];
    int s = 0;
    #pragma unroll
    for (int i = 0; i < PER; i++) {
        int n = base + i;
        local[i] = s;
        s += (n < NN) ? d_deg[n] : 0;
    }
    sums[t] = s;
    __syncthreads();
    for (int dd = 1; dd < SCAN_T; dd <<= 1) {
        int v = (t >= dd) ? sums[t - dd] : 0;
        __syncthreads();
        if (t >= dd) sums[t] += v;
        __syncthreads();
    }
    int exclBase = sums[t] - s;   // exclusive prefix for this thread's segment
    #pragma unroll
    for (int i = 0; i < PER; i++) {
        int n = base + i;
        if (n < NN) {
            int rp = exclBase + local[i];
            d_rowptr[n] = rp;
            d_cursor[n] = rp;
            d_dinv[n] = rsqrtf((float)(d_deg[n] + 1));   // +1 self-loop
        }
    }
    if (t == SCAN_T - 1) d_rowptr[NN] = sums[SCAN_T - 1];
}

__global__ void k_fill(const int* __restrict__ src, const int* __restrict__ dst) {
    int e = blockIdx.x * blockDim.x + threadIdx.x;
    if (e < NE) {
        int s = src[e], d = dst[e];
        if ((unsigned)s < NN && (unsigned)d < NN) {
            int pos = atomicAdd(&d_cursor[d], 1);
            d_csr[pos] = s;
        }
    }
}

// ---------------- layer-1 pre-scale: g0 = dinv[r] * x ----------------------
__global__ void k_scale0(const float* __restrict__ x) {
    const int R4 = F0 / 4;                       // 25 float4 per row
    size_t idx = (size_t)blockIdx.x * blockDim.x + threadIdx.x;
    const size_t total = (size_t)NN * R4;
    if (idx >= total) return;
    int r = (int)(idx / R4);
    float s = d_dinv[r];
    float4 v = ((const float4*)x)[idx];
    v.x *= s; v.y *= s; v.z *= s; v.w *= s;
    ((float4*)d_g0)[idx] = v;
}

// ---------------- layer-1 gather: agg0[d] = g0[d] + sum_{s in N(d)} g0[s] ---
__global__ void k_gather1() {
    const int R4 = F0 / 4;                       // 25
    int w = (blockIdx.x * blockDim.x + threadIdx.x) >> 5;
    int lane = threadIdx.x & 31;
    if (w >= NN) return;
    const float4* G = (const float4*)d_g0;
    float4 acc = make_float4(0.f, 0.f, 0.f, 0.f);
    if (lane < R4) acc = G[(size_t)w * R4 + lane];        // self-loop seed
    int b = d_rowptr[w], e = d_rowptr[w + 1];
    for (int j = b; j < e; j++) {
        int s = d_csr[j];                                  // broadcast load
        if (lane < R4) {
            float4 v = G[(size_t)s * R4 + lane];
            acc.x += v.x; acc.y += v.y; acc.z += v.z; acc.w += v.w;
        }
    }
    if (lane < R4) ((float4*)d_agg0)[(size_t)w * R4 + lane] = acc;
}

// ---------------- SGEMM, BM=128 x BN=64 x BK=16, 8x4 per thread ------------
// L==1: A = dinv[r]*agg0 (scaled at load), C = relu(acc + b1) -> d_relu1
// L==2: A = d_relu1,                       C = dinv[r]*acc -> d_g2
#define BM 128
#define BN 64
#define BK 16

template <int L>
__global__ void k_gemm_impl(const float* __restrict__ B,
                            const float* __restrict__ bias,
                            int M, int N, int K) {
    const float* __restrict__ A = (L == 1) ? d_agg0 : d_relu1;

    __shared__ float As[BK][BM + 4];
    __shared__ float Bs[BK][BN];
    int tid = threadIdx.x;
    int tx = tid & 15, ty = tid >> 4;
    int rowBase = blockIdx.y * BM;
    int colBase = blockIdx.x * BN;
    float acc[8][4] = {};

    for (int k0 = 0; k0 < K; k0 += BK) {
        #pragma unroll
        for (int i = tid; i < BM * BK; i += 256) {
            int r = i >> 4, c = i & 15;
            int gr = rowBase + r, gc = k0 + c;
            float v = (gr < M && gc < K) ? A[(size_t)gr * K + gc] : 0.0f;
            if (L == 1 && gr < M) v *= d_dinv[gr];   // fold dinv into A
            As[c][r] = v;
        }
        #pragma unroll
        for (int i = tid; i < BK * BN; i += 256) {
            int r = i >> 6, c = i & 63;
            int gr = k0 + r, gc = colBase + c;
            Bs[r][c] = (gr < K && gc < N) ? B[(size_t)gr * N + gc] : 0.0f;
        }
        __syncthreads();
        #pragma unroll
        for (int k = 0; k < BK; k++) {
            float a[8], b[4];
            #pragma unroll
            for (int i = 0; i < 8; i++) a[i] = As[k][ty * 8 + i];
            #pragma unroll
            for (int j = 0; j < 4; j++) b[j] = Bs[k][tx * 4 + j];
            #pragma unroll
            for (int i = 0; i < 8; i++)
                #pragma unroll
                for (int j = 0; j < 4; j++) acc[i][j] += a[i] * b[j];
        }
        __syncthreads();
    }

    #pragma unroll
    for (int i = 0; i < 8; i++) {
        int r = rowBase + ty * 8 + i;
        if (r >= M) continue;
        if (L == 1) {
            #pragma unroll
            for (int j = 0; j < 4; j++) {
                int c = colBase + tx * 4 + j;
                d_relu1[(size_t)r * N + c] = fmaxf(acc[i][j] + bias[c], 0.0f);
            }
        } else {
            float s = d_dinv[r];
            #pragma unroll
            for (int j = 0; j < 4; j++) {
                int c = colBase + tx * 4 + j;
                d_g2[(size_t)r * N + c] = acc[i][j] * s;
            }
        }
    }
}

// ---------------- layer-2 gather fused with finalize + FC head -------------
// agg row accumulated in registers, then out[d] = dot(relu(dinv*agg+b2), Wfc)+bfc
__global__ void k_gather2_fc(const float* __restrict__ b2,
                             const float* __restrict__ Wfc,
                             const float* __restrict__ bfc,
                             float* __restrict__ out) {
    const int R4 = F2 / 4;                       // 32: one float4 per lane
    int w = (blockIdx.x * blockDim.x + threadIdx.x) >> 5;
    int lane = threadIdx.x & 31;
    if (w >= NN) return;
    const float4* G = (const float4*)d_g2;
    float4 acc = G[(size_t)w * R4 + lane];                // self-loop seed
    int b = d_rowptr[w], e = d_rowptr[w + 1];
    for (int j = b; j < e; j++) {
        int s = d_csr[j];
        float4 v = G[(size_t)s * R4 + lane];
        acc.x += v.x; acc.y += v.y; acc.z += v.z; acc.w += v.w;
    }
    float sc = d_dinv[w];
    float4 bb = ((const float4*)b2)[lane];
    float4 wf = ((const float4*)Wfc)[lane];
    float dot = fmaxf(fmaf(acc.x, sc, bb.x), 0.0f) * wf.x
              + fmaxf(fmaf(acc.y, sc, bb.y), 0.0f) * wf.y
              + fmaxf(fmaf(acc.z, sc, bb.z), 0.0f) * wf.z
              + fmaxf(fmaf(acc.w, sc, bb.w), 0.0f) * wf.w;
    #pragma unroll
    for (int o = 16; o > 0; o >>= 1) dot += __shfl_down_sync(0xffffffffu, dot, o);
    if (lane == 0) out[w] = dot + bfc[0];
}

// ---------------- launch ----------------------------------------------------
extern "C" void kernel_launch(void* const* d_in, const int* in_sizes, int n_in,
                              void* d_out, int out_size) {
    const float* x   = (const float*)d_in[0];
    const int*   ei  = (const int*)d_in[1];    // [2, NE] int32
    const float* W1  = (const float*)d_in[2];
    const float* b1  = (const float*)d_in[3];
    const float* W2  = (const float*)d_in[4];
    const float* b2  = (const float*)d_in[5];
    const float* Wfc = (const float*)d_in[6];
    const float* bfc = (const float*)d_in[7];
    float* out = (float*)d_out;

    const int* src = ei;
    const int* dst = ei + NE;

    // CSR build (by dst) + dinv
    k_zero_deg<<<(NN + 255) / 256, 256>>>();
    k_count<<<(NE + 255) / 256, 256>>>(dst);
    k_scan<<<1, SCAN_T>>>();
    k_fill<<<(NE + 255) / 256, 256>>>(src, dst);

    // layer 1: scale x, gather (F=100), GEMM with fused relu+bias
    k_scale0<<<((NN * (F0 / 4)) + 255) / 256, 256>>>(x);
    k_gather1<<<(NN * 32 + 255) / 256, 256>>>();
    {
        dim3 grid(F1 / BN, (NN + BM - 1) / BM);
        k_gemm_impl<1><<<grid, 256>>>(W1, b1, NN, F1, F0);
    }

    // layer 2: GEMM, then gather fused with finalize + FC head
    {
        dim3 grid(F2 / BN, (NN + BM - 1) / BM);
        k_gemm_impl<2><<<grid, 256>>>(W2, nullptr, NN, F2, F1);
    }
    k_gather2_fc<<<(NN * 32 + 255) / 256, 256>>>(b2, Wfc, bfc, out);
}

// round 10
// speedup vs baseline: 1.6337x; 1.6337x over previous
#include <cuda_runtime.h>
#include <cstdint>

#define NN 50000
#define NE 800000
#define F0 100
#define F1 256
#define F2 128

// ---------------- scratch (static device globals; no allocations) ----------
__device__ __align__(16) float d_dinv[NN];                 // deg then rsqrt(deg)
__device__ __align__(16) float d_g0[(size_t)NN * F0];      // dinv-scaled x
__device__ __align__(16) float d_agg0[(size_t)NN * F0];    // layer-1 aggregation (init = g0)
__device__ __align__(16) float d_relu1[(size_t)NN * F1];   // layer-1 activation
__device__ __align__(16) float d_g2[(size_t)NN * F2];      // dinv-scaled h2
__device__ __align__(16) float d_agg2[(size_t)NN * F2];    // layer-2 aggregation (init = g2)

// ---------------- degree / normalization ----------------------------------
__global__ void k_init_deg() {
    int i = blockIdx.x * blockDim.x + threadIdx.x;
    if (i < NN) d_dinv[i] = 1.0f;   // self-loop contributes 1
}

__global__ void k_edge_deg(const int* __restrict__ dst) {
    int e = blockIdx.x * blockDim.x + threadIdx.x;
    if (e < NE) {
        int d = dst[e];
        if ((unsigned)d < NN) atomicAdd(&d_dinv[d], 1.0f);
    }
}

__global__ void k_rsqrt() {
    int i = blockIdx.x * blockDim.x + threadIdx.x;
    if (i < NN) d_dinv[i] = rsqrtf(d_dinv[i]);
}

// ---------------- layer-1 pre-scale: g0 = agg0 = dinv[r] * x ---------------
__global__ void k_scale0(const float* __restrict__ x) {
    const int R4 = F0 / 4;                       // 25 float4 per row
    size_t idx = (size_t)blockIdx.x * blockDim.x + threadIdx.x;
    const size_t total = (size_t)NN * R4;
    if (idx >= total) return;
    int r = (int)(idx / R4);
    float s = d_dinv[r];
    float4 v = ((const float4*)x)[idx];
    v.x *= s; v.y *= s; v.z *= s; v.w *= s;
    ((float4*)d_g0)[idx] = v;
    ((float4*)d_agg0)[idx] = v;                  // self-loop term pre-seeded
}

// ---------------- edge scatter with vector red.global ----------------------
__device__ __forceinline__ void red_add_v4(float* p, float4 v) {
    asm volatile("red.global.add.v4.f32 [%0], {%1, %2, %3, %4};"
                 :: "l"(p), "f"(v.x), "f"(v.y), "f"(v.z), "f"(v.w)
                 : "memory");
}

template <int L>
__global__ void k_scatter(const int* __restrict__ src,
                          const int* __restrict__ dst) {
    const float* __restrict__ G   = (L == 1) ? d_g0   : d_g2;
    float* __restrict__ AGG       = (L == 1) ? d_agg0 : d_agg2;
    const int F  = (L == 1) ? F0 : F2;
    const int F4 = F / 4;                        // 25 or 32

    int w = (blockIdx.x * blockDim.x + threadIdx.x) >> 5;
    int lane = threadIdx.x & 31;
    if (w >= NE) return;
    int s = src[w], d = dst[w];
    if ((unsigned)s >= NN || (unsigned)d >= NN) return;
    if (lane < F4) {
        float4 v = ((const float4*)(G + (size_t)s * F))[lane];
        red_add_v4(AGG + (size_t)d * F + 4 * lane, v);
    }
}

// ---------------- tf32 tensor-core GEMM ------------------------------------
// BM=128 x BN=64 x BK=32; 256 threads = 8 warps as 4(m) x 2(n); warp tile
// 32x32 = 2(m16) x 4(n8) mma.sync.m16n8k8 tiles. Operands tf32-rounded at
// smem store; fp32 accumulate.
// L==1: A = dinv[r]*agg0 (folded at load), C = relu(acc + b1) -> d_relu1
// L==2: A = d_relu1,                       C = dinv[r]*acc -> d_g2, d_agg2
#define BM 128
#define BN 64
#define BK 32
#define AST 36   // As row stride (floats): perfect fragment-load banking
#define BST 37   // Bs row stride (floats): conflict-free transpose store

__device__ __forceinline__ float to_tf32(float x) {
    float y;
    asm("cvt.rna.tf32.f32 %0, %1;" : "=f"(y) : "f"(x));
    return y;
}

__device__ __forceinline__ void mma_tf32(float* c, const uint32_t* a, const uint32_t* b) {
    asm volatile(
        "mma.sync.aligned.m16n8k8.row.col.f32.tf32.tf32.f32 "
        "{%0,%1,%2,%3}, {%4,%5,%6,%7}, {%8,%9}, {%0,%1,%2,%3};"
        : "+f"(c[0]), "+f"(c[1]), "+f"(c[2]), "+f"(c[3])
        : "r"(a[0]), "r"(a[1]), "r"(a[2]), "r"(a[3]), "r"(b[0]), "r"(b[1]));
}

template <int L>
__global__ void k_gemm_tc(const float* __restrict__ Bg,
                          const float* __restrict__ bias,
                          int M, int N, int K) {
    const float* __restrict__ A = (L == 1) ? d_agg0 : d_relu1;

    __shared__ float As[BM * AST];
    __shared__ float Bs[BN * BST];

    int tid  = threadIdx.x;
    int lane = tid & 31, wrp = tid >> 5;
    int wm = wrp >> 1, wn = wrp & 1;
    int gid = lane >> 2, tig = lane & 3;        // groupID, threadID-in-group
    int rowBase = blockIdx.y * BM;
    int colBase = blockIdx.x * BN;

    float acc[2][4][4];
    #pragma unroll
    for (int i = 0; i < 2; i++)
        #pragma unroll
        for (int j = 0; j < 4; j++)
            #pragma unroll
            for (int k = 0; k < 4; k++) acc[i][j][k] = 0.0f;

    for (int k0 = 0; k0 < K; k0 += BK) {
        // ---- stage A tile (BM x BK = 1024 float4, 4 per thread) ----
        #pragma unroll
        for (int it = 0; it < 4; it++) {
            int f = tid + 256 * it;             // float4 index in tile
            int m = f >> 3, kq = (f & 7) << 2;  // 8 float4 per row
            int gr = rowBase + m, gc = k0 + kq;
            float4 v = make_float4(0.f, 0.f, 0.f, 0.f);
            if (gr < M && gc + 4 <= K)
                v = *(const float4*)(A + (size_t)gr * K + gc);
            if (L == 1) {
                float s = (gr < M) ? d_dinv[gr] : 0.0f;
                v.x *= s; v.y *= s; v.z *= s; v.w *= s;
            }
            float4 t;
            t.x = to_tf32(v.x); t.y = to_tf32(v.y);
            t.z = to_tf32(v.z); t.w = to_tf32(v.w);
            *(float4*)(As + m * AST + kq) = t;
        }
        // ---- stage B tile transposed (BK x BN -> Bs[n][k], 2 float4/thr) ----
        #pragma unroll
        for (int it = 0; it < 2; it++) {
            int f = tid + 256 * it;             // float4 index
            int kk = f >> 4, nq = (f & 15) << 2;  // 16 float4 per k-row
            int gr = k0 + kk, gc = colBase + nq;
            float4 v = make_float4(0.f, 0.f, 0.f, 0.f);
            if (gr < K)
                v = *(const float4*)(Bg + (size_t)gr * N + gc);
            Bs[(nq + 0) * BST + kk] = to_tf32(v.x);
            Bs[(nq + 1) * BST + kk] = to_tf32(v.y);
            Bs[(nq + 2) * BST + kk] = to_tf32(v.z);
            Bs[(nq + 3) * BST + kk] = to_tf32(v.w);
        }
        __syncthreads();

        // ---- compute: 4 k8 steps ----
        #pragma unroll
        for (int kb = 0; kb < BK; kb += 8) {
            uint32_t afr[2][4], bfr[4][2];
            #pragma unroll
            for (int mt = 0; mt < 2; mt++) {
                const float* p = As + (wm * 32 + mt * 16 + gid) * AST + kb + tig;
                afr[mt][0] = __float_as_uint(p[0]);
                afr[mt][1] = __float_as_uint(p[8 * AST]);
                afr[mt][2] = __float_as_uint(p[4]);
                afr[mt][3] = __float_as_uint(p[8 * AST + 4]);
            }
            #pragma unroll
            for (int nt = 0; nt < 4; nt++) {
                const float* p = Bs + (wn * 32 + nt * 8 + gid) * BST + kb + tig;
                bfr[nt][0] = __float_as_uint(p[0]);
                bfr[nt][1] = __float_as_uint(p[4]);
            }
            #pragma unroll
            for (int mt = 0; mt < 2; mt++)
                #pragma unroll
                for (int nt = 0; nt < 4; nt++)
                    mma_tf32(acc[mt][nt], afr[mt], bfr[nt]);
        }
        __syncthreads();
    }

    // ---- epilogue ----
    #pragma unroll
    for (int mt = 0; mt < 2; mt++) {
        int r0 = rowBase + wm * 32 + mt * 16 + gid;
        int r1 = r0 + 8;
        #pragma unroll
        for (int nt = 0; nt < 4; nt++) {
            int c = colBase + wn * 32 + nt * 8 + tig * 2;
            float* a4 = acc[mt][nt];
            if (L == 1) {
                float bx = bias[c], by = bias[c + 1];
                if (r0 < M) {
                    float2 v = make_float2(fmaxf(a4[0] + bx, 0.f), fmaxf(a4[1] + by, 0.f));
                    *(float2*)(d_relu1 + (size_t)r0 * N + c) = v;
                }
                if (r1 < M) {
                    float2 v = make_float2(fmaxf(a4[2] + bx, 0.f), fmaxf(a4[3] + by, 0.f));
                    *(float2*)(d_relu1 + (size_t)r1 * N + c) = v;
                }
            } else {
                if (r0 < M) {
                    float s = d_dinv[r0];
                    float2 v = make_float2(a4[0] * s, a4[1] * s);
                    *(float2*)(d_g2 + (size_t)r0 * N + c) = v;
                    *(float2*)(d_agg2 + (size_t)r0 * N + c) = v;   // seed self-loop
                }
                if (r1 < M) {
                    float s = d_dinv[r1];
                    float2 v = make_float2(a4[2] * s, a4[3] * s);
                    *(float2*)(d_g2 + (size_t)r1 * N + c) = v;
                    *(float2*)(d_agg2 + (size_t)r1 * N + c) = v;
                }
            }
        }
    }
}

// ---------------- finalize layer 2 fused with FC head ----------------------
__global__ void k_fc(const float* __restrict__ b2, const float* __restrict__ Wfc,
                     const float* __restrict__ bfc, float* __restrict__ out) {
    int w = (blockIdx.x * blockDim.x + threadIdx.x) >> 5;
    int lane = threadIdx.x & 31;
    if (w >= NN) return;
    float s = d_dinv[w];
    float4 a = ((const float4*)(d_agg2 + (size_t)w * F2))[lane];  // F2/4 == 32
    float4 bb = ((const float4*)b2)[lane];
    float4 wf = ((const float4*)Wfc)[lane];
    float acc = fmaxf(fmaf(a.x, s, bb.x), 0.0f) * wf.x
              + fmaxf(fmaf(a.y, s, bb.y), 0.0f) * wf.y
              + fmaxf(fmaf(a.z, s, bb.z), 0.0f) * wf.z
              + fmaxf(fmaf(a.w, s, bb.w), 0.0f) * wf.w;
    #pragma unroll
    for (int o = 16; o > 0; o >>= 1) acc += __shfl_down_sync(0xffffffffu, acc, o);
    if (lane == 0) out[w] = acc + bfc[0];
}

// ---------------- launch ----------------------------------------------------
extern "C" void kernel_launch(void* const* d_in, const int* in_sizes, int n_in,
                              void* d_out, int out_size) {
    const float* x   = (const float*)d_in[0];
    const int*   ei  = (const int*)d_in[1];    // [2, NE] int32
    const float* W1  = (const float*)d_in[2];
    const float* b1  = (const float*)d_in[3];
    const float* W2  = (const float*)d_in[4];
    const float* b2  = (const float*)d_in[5];
    const float* Wfc = (const float*)d_in[6];
    const float* bfc = (const float*)d_in[7];
    float* out = (float*)d_out;

    const int* src = ei;
    const int* dst = ei + NE;

    // degree + normalization
    k_init_deg<<<(NN + 255) / 256, 256>>>();
    k_edge_deg<<<(NE + 255) / 256, 256>>>(dst);
    k_rsqrt<<<(NN + 255) / 256, 256>>>();

    // layer 1: scale x (seeds agg0), scatter-aggregate at F=100, tf32 GEMM
    k_scale0<<<((NN * (F0 / 4)) + 255) / 256, 256>>>(x);
    k_scatter<1><<<(NE * 32 + 255) / 256, 256>>>(src, dst);
    {
        dim3 grid(F1 / BN, (NN + BM - 1) / BM);
        k_gemm_tc<1><<<grid, 256>>>(W1, b1, NN, F1, F0);
    }

    // layer 2: tf32 GEMM (seeds agg2), scatter-aggregate at F=128
    {
        dim3 grid(F2 / BN, (NN + BM - 1) / BM);
        k_gemm_tc<2><<<grid, 256>>>(W2, nullptr, NN, F2, F1);
    }
    k_scatter<2><<<(NE * 32 + 255) / 256, 256>>>(src, dst);

    // finalize layer 2 + FC head
    k_fc<<<(NN * 32 + 255) / 256, 256>>>(b2, Wfc, bfc, out);
}

// round 13
// speedup vs baseline: 2.3530x; 1.4403x over previous
#include <cuda_runtime.h>
#include <cstdint>

#define NN 50000
#define NE 800000
#define F0 100
#define F1 256
#define F2 128

// ---------------- scratch (static device globals; no allocations) ----------
__device__ __align__(16) float d_dinv[NN];                 // rsqrt(deg+1)
__device__ int d_deg[NN];                                  // int degree (no self-loop)
__device__ __align__(16) float d_g0[(size_t)NN * F0];      // dinv-scaled x
__device__ __align__(16) float d_agg0[(size_t)NN * F0];    // layer-1 aggregation (init = g0)
__device__ __align__(16) float d_relu1[(size_t)NN * F1];   // layer-1 activation
__device__ __align__(16) float d_g2[(size_t)NN * F2];      // dinv-scaled h2
__device__ __align__(16) float d_agg2[(size_t)NN * F2];    // layer-2 aggregation (init = g2)

// ---------------- degree -----------------------------------------------------
__global__ void k_zero_deg() {
    int i = blockIdx.x * blockDim.x + threadIdx.x;
    if (i < NN) d_deg[i] = 0;
}

__global__ void k_count(const int* __restrict__ dst) {
    int e = blockIdx.x * blockDim.x + threadIdx.x;
    if (e < NE) {
        int d = dst[e];
        if ((unsigned)d < NN) atomicAdd(&d_deg[d], 1);
    }
}

// ---------------- dinv + layer-1 pre-scale (warp per row) -------------------
__global__ void k_dinv_scale(const float* __restrict__ x) {
    int w = (blockIdx.x * blockDim.x + threadIdx.x) >> 5;
    int lane = threadIdx.x & 31;
    if (w >= NN) return;
    float s = 0.0f;
    if (lane == 0) s = rsqrtf((float)(d_deg[w] + 1));   // +1 self-loop
    s = __shfl_sync(0xffffffffu, s, 0);
    if (lane == 0) d_dinv[w] = s;
    if (lane < F0 / 4) {
        float4 v = ((const float4*)(x + (size_t)w * F0))[lane];
        v.x *= s; v.y *= s; v.z *= s; v.w *= s;
        ((float4*)(d_g0 + (size_t)w * F0))[lane] = v;
        ((float4*)(d_agg0 + (size_t)w * F0))[lane] = v;   // self-loop seed
    }
}

// ---------------- edge scatter with vector red.global -----------------------
__device__ __forceinline__ void red_add_v4(float* p, float4 v) {
    asm volatile("red.global.add.v4.f32 [%0], {%1, %2, %3, %4};"
                 :: "l"(p), "f"(v.x), "f"(v.y), "f"(v.z), "f"(v.w)
                 : "memory");
}

template <int L>
__global__ void k_scatter(const int* __restrict__ src,
                          const int* __restrict__ dst) {
    const float* __restrict__ G = (L == 1) ? d_g0   : d_g2;
    float* __restrict__ AGG     = (L == 1) ? d_agg0 : d_agg2;
    const int F  = (L == 1) ? F0 : F2;
    const int F4 = F / 4;                        // 25 or 32

    int w = (blockIdx.x * blockDim.x + threadIdx.x) >> 5;
    int lane = threadIdx.x & 31;
    if (w >= NE) return;
    int s = src[w], d = dst[w];
    if ((unsigned)s >= NN || (unsigned)d >= NN) return;
    if (lane < F4) {
        float4 v = ((const float4*)(G + (size_t)s * F))[lane];
        red_add_v4(AGG + (size_t)d * F + 4 * lane, v);
    }
}

// ---------------- tf32 tensor-core GEMM, cp.async double-buffered ----------
// BM=128 x BN=64 x BK=32, 256 thr = 8 warps (4m x 2n), warp tile 32x32 =
// 2(m16) x 4(n8) mma.m16n8k8. XOR-swizzled smem (no padding): 2 stages fit
// in exactly 48KB static. tf32 conversion at fragment-load time.
// L==1: A = agg0, C = relu(dinv[r]*acc + b1) -> d_relu1   (dinv folded in epi)
// L==2: A = d_relu1, C = dinv[r]*acc -> d_g2 and d_agg2
#define BM 128
#define BN 64
#define BK 32

__device__ __forceinline__ float to_tf32(float x) {
    float y;
    asm("cvt.rna.tf32.f32 %0, %1;" : "=f"(y) : "f"(x));
    return y;
}

__device__ __forceinline__ void mma_tf32(float* c, const uint32_t* a, const uint32_t* b) {
    asm volatile(
        "mma.sync.aligned.m16n8k8.row.col.f32.tf32.tf32.f32 "
        "{%0,%1,%2,%3}, {%4,%5,%6,%7}, {%8,%9}, {%0,%1,%2,%3};"
        : "+f"(c[0]), "+f"(c[1]), "+f"(c[2]), "+f"(c[3])
        : "r"(a[0]), "r"(a[1]), "r"(a[2]), "r"(a[3]), "r"(b[0]), "r"(b[1]));
}

__device__ __forceinline__ uint32_t smem_u32(const void* p) {
    return (uint32_t)__cvta_generic_to_shared(p);
}
__device__ __forceinline__ void cp16(uint32_t dst, const void* src, int sz) {
    asm volatile("cp.async.ca.shared.global [%0], [%1], 16, %2;"
                 :: "r"(dst), "l"(src), "r"(sz));
}
__device__ __forceinline__ void cp_commit() {
    asm volatile("cp.async.commit_group;");
}
template <int Ng>
__device__ __forceinline__ void cp_wait() {
    asm volatile("cp.async.wait_group %0;" :: "n"(Ng));
}

template <int L>
__global__ void k_gemm_tc(const float* __restrict__ Bg,
                          const float* __restrict__ bias,
                          int M, int N, int K) {
    const float* __restrict__ A = (L == 1) ? d_agg0 : d_relu1;

    __shared__ float As[2][BM * BK];   // 32 KB   (swizzle: chunk ^= m&7)
    __shared__ float Bs[2][BK * BN];   // 16 KB   (swizzle: chunk ^= (k&3)<<2)

    int tid = threadIdx.x;
    int lane = tid & 31, wrp = tid >> 5;
    int wm = wrp >> 1, wn = wrp & 1;
    int gid = lane >> 2, tig = lane & 3;
    int rowBase = blockIdx.y * BM;
    int colBase = blockIdx.x * BN;

    float acc[2][4][4] = {};
    const int KT = (K + BK - 1) / BK;

    auto load_tile = [&](int buf, int k0) {
        // A tile: 128x32 = 1024 float4, 4 per thread
        #pragma unroll
        for (int it = 0; it < 4; it++) {
            int f = tid + 256 * it;
            int m = f >> 3, kq4 = f & 7;
            int gr = rowBase + m, gc = k0 + kq4 * 4;
            const float* src = A;
            int sz = 0;
            if (gr < M && gc + 4 <= K) { src = A + (size_t)gr * K + gc; sz = 16; }
            cp16(smem_u32(&As[buf][m * BK + 4 * (kq4 ^ (m & 7))]), src, sz);
        }
        // B tile: 32x64 = 512 float4, 2 per thread
        #pragma unroll
        for (int it = 0; it < 2; it++) {
            int f = tid + 256 * it;
            int kk = f >> 4, nq4 = f & 15;
            int gr = k0 + kk, gc = colBase + nq4 * 4;
            const float* src = Bg;
            int sz = 0;
            if (gr < K) { src = Bg + (size_t)gr * N + gc; sz = 16; }
            cp16(smem_u32(&Bs[buf][kk * BN + 4 * (nq4 ^ ((kk & 3) << 2))]), src, sz);
        }
        cp_commit();
    };

    load_tile(0, 0);

    for (int kt = 0; kt < KT; kt++) {
        if (kt + 1 < KT) {
            load_tile((kt + 1) & 1, (kt + 1) * BK);
            cp_wait<1>();
        } else {
            cp_wait<0>();
        }
        __syncthreads();

        const float* as = As[kt & 1];
        const float* bs = Bs[kt & 1];
        #pragma unroll
        for (int kb = 0; kb < BK; kb += 8) {
            uint32_t afr[2][4], bfr[4][2];
            int c0 = kb >> 2;
            #pragma unroll
            for (int mt = 0; mt < 2; mt++) {
                int r0 = wm * 32 + mt * 16 + gid;
                int r1 = r0 + 8;
                int s0 = r0 & 7;                 // (r1 & 7) == s0
                afr[mt][0] = __float_as_uint(to_tf32(as[r0 * BK + 4 * (c0 ^ s0) + tig]));
                afr[mt][1] = __float_as_uint(to_tf32(as[r1 * BK + 4 * (c0 ^ s0) + tig]));
                afr[mt][2] = __float_as_uint(to_tf32(as[r0 * BK + 4 * ((c0 + 1) ^ s0) + tig]));
                afr[mt][3] = __float_as_uint(to_tf32(as[r1 * BK + 4 * ((c0 + 1) ^ s0) + tig]));
            }
            #pragma unroll
            for (int nt = 0; nt < 4; nt++) {
                int n = wn * 32 + nt * 8 + gid;
                int n4 = n >> 2, nl = n & 3;
                int kA = kb + tig;               // kA&3 == tig, (kA+4)&3 == tig
                bfr[nt][0] = __float_as_uint(to_tf32(bs[kA * BN + 4 * (n4 ^ (tig << 2)) + nl]));
                bfr[nt][1] = __float_as_uint(to_tf32(bs[(kA + 4) * BN + 4 * (n4 ^ (tig << 2)) + nl]));
            }
            #pragma unroll
            for (int mt = 0; mt < 2; mt++)
                #pragma unroll
                for (int nt = 0; nt < 4; nt++)
                    mma_tf32(acc[mt][nt], afr[mt], bfr[nt]);
        }
        __syncthreads();
    }

    // ---- epilogue ----
    #pragma unroll
    for (int mt = 0; mt < 2; mt++) {
        int r0 = rowBase + wm * 32 + mt * 16 + gid;
        int r1 = r0 + 8;
        float s0 = (r0 < M) ? d_dinv[r0] : 0.0f;
        float s1 = (r1 < M) ? d_dinv[r1] : 0.0f;
        #pragma unroll
        for (int nt = 0; nt < 4; nt++) {
            int c = colBase + wn * 32 + nt * 8 + tig * 2;
            float* a4 = acc[mt][nt];
            if (L == 1) {
                float bx = bias[c], by = bias[c + 1];
                if (r0 < M) {
                    float2 v = make_float2(fmaxf(fmaf(a4[0], s0, bx), 0.f),
                                           fmaxf(fmaf(a4[1], s0, by), 0.f));
                    *(float2*)(d_relu1 + (size_t)r0 * N + c) = v;
                }
                if (r1 < M) {
                    float2 v = make_float2(fmaxf(fmaf(a4[2], s1, bx), 0.f),
                                           fmaxf(fmaf(a4[3], s1, by), 0.f));
                    *(float2*)(d_relu1 + (size_t)r1 * N + c) = v;
                }
            } else {
                if (r0 < M) {
                    float2 v = make_float2(a4[0] * s0, a4[1] * s0);
                    *(float2*)(d_g2 + (size_t)r0 * N + c) = v;
                    *(float2*)(d_agg2 + (size_t)r0 * N + c) = v;   // self-loop seed
                }
                if (r1 < M) {
                    float2 v = make_float2(a4[2] * s1, a4[3] * s1);
                    *(float2*)(d_g2 + (size_t)r1 * N + c) = v;
                    *(float2*)(d_agg2 + (size_t)r1 * N + c) = v;
                }
            }
        }
    }
}

// ---------------- finalize layer 2 fused with FC head ----------------------
__global__ void k_fc(const float* __restrict__ b2, const float* __restrict__ Wfc,
                     const float* __restrict__ bfc, float* __restrict__ out) {
    int w = (blockIdx.x * blockDim.x + threadIdx.x) >> 5;
    int lane = threadIdx.x & 31;
    if (w >= NN) return;
    float s = d_dinv[w];
    float4 a = ((const float4*)(d_agg2 + (size_t)w * F2))[lane];  // F2/4 == 32
    float4 bb = ((const float4*)b2)[lane];
    float4 wf = ((const float4*)Wfc)[lane];
    float acc = fmaxf(fmaf(a.x, s, bb.x), 0.0f) * wf.x
              + fmaxf(fmaf(a.y, s, bb.y), 0.0f) * wf.y
              + fmaxf(fmaf(a.z, s, bb.z), 0.0f) * wf.z
              + fmaxf(fmaf(a.w, s, bb.w), 0.0f) * wf.w;
    #pragma unroll
    for (int o = 16; o > 0; o >>= 1) acc += __shfl_down_sync(0xffffffffu, acc, o);
    if (lane == 0) out[w] = acc + bfc[0];
}

// ---------------- launch ----------------------------------------------------
extern "C" void kernel_launch(void* const* d_in, const int* in_sizes, int n_in,
                              void* d_out, int out_size) {
    const float* x   = (const float*)d_in[0];
    const int*   ei  = (const int*)d_in[1];    // [2, NE] int32
    const float* W1  = (const float*)d_in[2];
    const float* b1  = (const float*)d_in[3];
    const float* W2  = (const float*)d_in[4];
    const float* b2  = (const float*)d_in[5];
    const float* Wfc = (const float*)d_in[6];
    const float* bfc = (const float*)d_in[7];
    float* out = (float*)d_out;

    const int* src = ei;
    const int* dst = ei + NE;

    // degree + dinv + layer-1 pre-scale
    k_zero_deg<<<(NN + 255) / 256, 256>>>();
    k_count<<<(NE + 255) / 256, 256>>>(dst);
    k_dinv_scale<<<(NN * 32 + 255) / 256, 256>>>(x);

    // layer 1: scatter-aggregate at F=100, pipelined tf32 GEMM (+relu+bias)
    k_scatter<1><<<(NE * 32 + 255) / 256, 256>>>(src, dst);
    {
        dim3 grid(F1 / BN, (NN + BM - 1) / BM);
        k_gemm_tc<1><<<grid, 256>>>(W1, b1, NN, F1, F0);
    }

    // layer 2: pipelined tf32 GEMM (seeds agg2), scatter-aggregate at F=128
    {
        dim3 grid(F2 / BN, (NN + BM - 1) / BM);
        k_gemm_tc<2><<<grid, 256>>>(W2, nullptr, NN, F2, F1);
    }
    k_scatter<2><<<(NE * 32 + 255) / 256, 256>>>(src, dst);

    // finalize layer 2 + FC head
    k_fc<<<(NN * 32 + 255) / 256, 256>>>(b2, Wfc, bfc, out);
}